// round 1
// baseline (speedup 1.0000x reference)
#include <cuda_runtime.h>

#define NN 50000
#define EE 800000
#define FF 512
#define HH 128
#define CC 40
#define NCAT 640   // (1 + 4) * 128

// ---------------- scratch (device globals; no allocation allowed) -----------
static __device__ __align__(256) float g_deg[NN];
static __device__ __align__(256) float g_norm[EE];
static __device__ __align__(256) float g_h [NN * HH];
static __device__ __align__(256) float g_hw[NN * HH];
static __device__ __align__(256) float g_t0[NN * HH];
static __device__ __align__(256) float g_t1[NN * HH];
static __device__ __align__(256) float g_cat[(size_t)NN * NCAT];

// ---------------- degree / norm ---------------------------------------------
__global__ void k_deg_init(float* __restrict__ deg) {
    int i = blockIdx.x * blockDim.x + threadIdx.x;
    if (i < NN) deg[i] = 1.0f;              // self-loop weight
}

__global__ void k_deg_acc(const int* __restrict__ ei, const float* __restrict__ ew,
                          float* __restrict__ deg) {
    int e = blockIdx.x * blockDim.x + threadIdx.x;
    if (e < EE) atomicAdd(&deg[ei[EE + e]], ew[e]);
}

__global__ void k_norm(const int* __restrict__ ei, const float* __restrict__ ew,
                       const float* __restrict__ deg, float* __restrict__ nrm) {
    int e = blockIdx.x * blockDim.x + threadIdx.x;
    if (e < EE) {
        float a = rsqrtf(deg[ei[e]]);
        float b = rsqrtf(deg[ei[EE + e]]);
        nrm[e] = a * ew[e] * b;
    }
}

// ---------------- SGEMM: C[M,128] = A[M,K] @ B[K,128] (+bias) ---------------
// 128x128 block tile, 256 threads, 8x8 per thread, BK=16.
__global__ __launch_bounds__(256) void k_sgemm(
    const float* __restrict__ A, const float* __restrict__ B,
    const float* __restrict__ bias, float* __restrict__ C,
    int M, int K, int ldc)
{
    __shared__ float As[16][128];
    __shared__ float Bs[16][128];

    const int block_row = blockIdx.x * 128;
    const int tid = threadIdx.x;
    const int tr = (tid / 16) * 8;   // row offset in tile
    const int tc = (tid % 16) * 8;   // col offset in tile

    float acc[8][8];
#pragma unroll
    for (int i = 0; i < 8; i++)
#pragma unroll
        for (int j = 0; j < 8; j++) acc[i][j] = 0.0f;

    for (int k0 = 0; k0 < K; k0 += 16) {
        // load A tile: 128 rows x 16 cols = 512 float4, 2 per thread
#pragma unroll
        for (int l = 0; l < 2; l++) {
            int v  = tid + l * 256;         // 0..511
            int r  = v >> 2;                // 0..127
            int c4 = (v & 3) * 4;           // 0,4,8,12
            float4 av = make_float4(0.f, 0.f, 0.f, 0.f);
            int grow = block_row + r;
            if (grow < M)
                av = *(const float4*)&A[(size_t)grow * K + k0 + c4];
            As[c4 + 0][r] = av.x;
            As[c4 + 1][r] = av.y;
            As[c4 + 2][r] = av.z;
            As[c4 + 3][r] = av.w;
        }
        // load B tile: 16 rows x 128 cols = 512 float4
#pragma unroll
        for (int l = 0; l < 2; l++) {
            int v  = tid + l * 256;
            int r  = v >> 5;                // 0..15
            int c4 = (v & 31) * 4;          // 0..124
            *(float4*)&Bs[r][c4] = *(const float4*)&B[(size_t)(k0 + r) * 128 + c4];
        }
        __syncthreads();

#pragma unroll
        for (int kk = 0; kk < 16; kk++) {
            float a[8], b[8];
#pragma unroll
            for (int i = 0; i < 8; i++) a[i] = As[kk][tr + i];
#pragma unroll
            for (int j = 0; j < 8; j++) b[j] = Bs[kk][tc + j];
#pragma unroll
            for (int i = 0; i < 8; i++)
#pragma unroll
                for (int j = 0; j < 8; j++) acc[i][j] += a[i] * b[j];
        }
        __syncthreads();
    }

#pragma unroll
    for (int i = 0; i < 8; i++) {
        int grow = block_row + tr + i;
        if (grow >= M) break;
#pragma unroll
        for (int j = 0; j < 8; j += 4) {
            float4 v;
            v.x = acc[i][j + 0];
            v.y = acc[i][j + 1];
            v.z = acc[i][j + 2];
            v.w = acc[i][j + 3];
            if (bias) {
                v.x += bias[tc + j + 0];
                v.y += bias[tc + j + 1];
                v.z += bias[tc + j + 2];
                v.w += bias[tc + j + 3];
            }
            *(float4*)&C[(size_t)grow * ldc + tc + j] = v;
        }
    }
}

// ---------------- GCN self-loop init: out = hw/deg + bias -------------------
__global__ void k_self(const float4* __restrict__ hw, const float* __restrict__ deg,
                       const float* __restrict__ bias, float4* __restrict__ out,
                       int ldo4) {
    int idx = blockIdx.x * blockDim.x + threadIdx.x;
    if (idx >= NN * 32) return;
    int node = idx >> 5, q = idx & 31;
    float r  = rsqrtf(deg[node]);
    float sn = r * r;                      // dinv[i]^2 (self-loop norm)
    float4 v = hw[idx];
    float4 bb = ((const float4*)bias)[q];
    float4 o;
    o.x = v.x * sn + bb.x;
    o.y = v.y * sn + bb.y;
    o.z = v.z * sn + bb.z;
    o.w = v.w * sn + bb.w;
    out[(size_t)node * ldo4 + q] = o;
}

// ---------------- edge scatter: out[dst] += norm * hw[src] ------------------
// warp per edge, float4 per lane, vector atomics (sm_90+)
__global__ __launch_bounds__(256) void k_scatter(
    const int* __restrict__ ei, const float* __restrict__ nrm,
    const float4* __restrict__ hw, float* __restrict__ out, int ldo)
{
    int g = blockIdx.x * blockDim.x + threadIdx.x;
    int e = g >> 5;
    if (e >= EE) return;
    int lane = g & 31;
    int s = __ldg(&ei[e]);
    int d = __ldg(&ei[EE + e]);
    float w = __ldg(&nrm[e]);
    float4 v = hw[(size_t)s * 32 + lane];
    v.x *= w; v.y *= w; v.z *= w; v.w *= w;
    float* dp = &out[(size_t)d * ldo + lane * 4];
#if __CUDA_ARCH__ >= 900
    atomicAdd((float4*)dp, v);
#else
    atomicAdd(dp + 0, v.x);
    atomicAdd(dp + 1, v.y);
    atomicAdd(dp + 2, v.z);
    atomicAdd(dp + 3, v.w);
#endif
}

// ---------------- h -> concat col 0 -----------------------------------------
__global__ void k_copy(const float4* __restrict__ src, float4* __restrict__ cat) {
    int idx = blockIdx.x * blockDim.x + threadIdx.x;
    if (idx >= NN * 32) return;
    int node = idx >> 5, q = idx & 31;
    cat[(size_t)node * (NCAT / 4) + q] = src[idx];
}

// ---------------- final: out = cat @ W_out + b_out --------------------------
__global__ void k_out(const float* __restrict__ cat, const float* __restrict__ W,
                      const float* __restrict__ b, float* __restrict__ out) {
    int idx = blockIdx.x * blockDim.x + threadIdx.x;
    if (idx >= NN * CC) return;
    int row = idx / CC, c = idx % CC;
    const float* a = &cat[(size_t)row * NCAT];
    float s = b[c];
#pragma unroll 8
    for (int k = 0; k < NCAT; k++) s += a[k] * __ldg(&W[k * CC + c]);
    out[idx] = s;
}

// ---------------- launch -----------------------------------------------------
extern "C" void kernel_launch(void* const* d_in, const int* in_sizes, int n_in,
                              void* d_out, int out_size) {
    const float* x     = (const float*)d_in[0];
    const int*   ei    = (const int*)  d_in[1];
    const float* ew    = (const float*)d_in[2];
    const float* W_in  = (const float*)d_in[3];
    const float* b_in  = (const float*)d_in[4];
    const float* W_gcn = (const float*)d_in[5];
    const float* b_gcn = (const float*)d_in[6];
    const float* W_out = (const float*)d_in[7];
    const float* b_out = (const float*)d_in[8];
    float* out = (float*)d_out;

    float *deg, *nrm, *h, *hw, *t0, *t1, *cat;
    cudaGetSymbolAddress((void**)&deg, g_deg);
    cudaGetSymbolAddress((void**)&nrm, g_norm);
    cudaGetSymbolAddress((void**)&h,   g_h);
    cudaGetSymbolAddress((void**)&hw,  g_hw);
    cudaGetSymbolAddress((void**)&t0,  g_t0);
    cudaGetSymbolAddress((void**)&t1,  g_t1);
    cudaGetSymbolAddress((void**)&cat, g_cat);

    // degree + norm
    k_deg_init<<<(NN + 255) / 256, 256>>>(deg);
    k_deg_acc <<<(EE + 255) / 256, 256>>>(ei, ew, deg);
    k_norm    <<<(EE + 255) / 256, 256>>>(ei, ew, deg, nrm);

    // h = x @ W_in + b_in ; cat[:, 0:128] = h
    k_sgemm<<<(NN + 127) / 128, 256>>>(x, W_in, b_in, h, NN, FF, HH);
    k_copy <<<(NN * 32 + 255) / 256, 256>>>((const float4*)h, (float4*)cat);

    // one GCN conv: dst = scatter(norm * (in@Wk)) + self + bias
    auto gcn = [&](const float* in, int k, float* dst, int ldo) {
        k_sgemm  <<<(NN + 127) / 128, 256>>>(in, W_gcn + (size_t)k * HH * HH,
                                             nullptr, hw, NN, HH, HH);
        k_self   <<<(NN * 32 + 255) / 256, 256>>>((const float4*)hw, deg,
                                                  b_gcn + (size_t)k * HH,
                                                  (float4*)dst, ldo / 4);
        k_scatter<<<(EE * 32 + 255) / 256, 256>>>(ei, nrm, (const float4*)hw,
                                                  dst, ldo);
    };

    // inception chains (k increments across chains)
    gcn(h,  0, cat + 1 * HH, NCAT);             // chain 1

    gcn(h,  1, t0, HH);                         // chain 2
    gcn(t0, 2, cat + 2 * HH, NCAT);

    gcn(h,  3, t0, HH);                         // chain 3
    gcn(t0, 4, t1, HH);
    gcn(t1, 5, cat + 3 * HH, NCAT);

    gcn(h,  6, t0, HH);                         // chain 4
    gcn(t0, 7, t1, HH);
    gcn(t1, 8, t0, HH);
    gcn(t0, 9, cat + 4 * HH, NCAT);

    // out = cat @ W_out + b_out
    k_out<<<(NN * CC + 255) / 256, 256>>>(cat, W_out, b_out, out);
}

// round 2
// speedup vs baseline: 1.6444x; 1.6444x over previous
#include <cuda_runtime.h>

#define NN 50000
#define EE 800000
#define FF 512
#define HH 128
#define CC 40
#define NCAT 640   // (1 + 4) * 128

// ---------------- scratch (device globals; no allocation allowed) -----------
static __device__ __align__(256) float g_deg[NN];
static __device__ __align__(256) float g_norm[EE];
static __device__ __align__(256) float g_hw[NN * HH];
static __device__ __align__(256) float g_t0[NN * HH];
static __device__ __align__(256) float g_t1[NN * HH];
static __device__ __align__(256) float g_cat[(size_t)NN * NCAT];
// CSR scratch
static __device__ __align__(256) int   g_cnt[NN];
static __device__ __align__(256) int   g_rowptr[NN + 1];
static __device__ __align__(256) int   g_cursor[NN];
static __device__ __align__(256) int   g_csrc[EE];
static __device__ __align__(256) float g_cw[EE];

// ---------------- degree / norm / CSR build ---------------------------------
__global__ void k_deg_init(float* __restrict__ deg, int* __restrict__ cnt) {
    int i = blockIdx.x * blockDim.x + threadIdx.x;
    if (i < NN) { deg[i] = 1.0f; cnt[i] = 0; }     // self-loop weight
}

__global__ void k_deg_acc(const int* __restrict__ ei, const float* __restrict__ ew,
                          float* __restrict__ deg, int* __restrict__ cnt) {
    int e = blockIdx.x * blockDim.x + threadIdx.x;
    if (e < EE) {
        int d = ei[EE + e];
        atomicAdd(&deg[d], ew[e]);
        atomicAdd(&cnt[d], 1);
    }
}

__global__ void k_norm(const int* __restrict__ ei, const float* __restrict__ ew,
                       const float* __restrict__ deg, float* __restrict__ nrm) {
    int e = blockIdx.x * blockDim.x + threadIdx.x;
    if (e < EE) {
        float a = rsqrtf(deg[ei[e]]);
        float b = rsqrtf(deg[ei[EE + e]]);
        nrm[e] = a * ew[e] * b;
    }
}

// single-block exclusive scan of cnt -> rowptr (+ cursor copy)
__global__ void k_scan(const int* __restrict__ cnt, int* __restrict__ rowptr,
                       int* __restrict__ cursor) {
    const int T = 1024;
    __shared__ int part[T];
    int tid = threadIdx.x;
    int chunk = (NN + T - 1) / T;
    int base = tid * chunk;
    int local = 0;
    for (int i = 0; i < chunk; i++) {
        int idx = base + i;
        if (idx < NN) local += cnt[idx];
    }
    part[tid] = local;
    __syncthreads();
    for (int off = 1; off < T; off <<= 1) {
        int v = (tid >= off) ? part[tid - off] : 0;
        __syncthreads();
        part[tid] += v;
        __syncthreads();
    }
    int run = part[tid] - local;            // exclusive prefix of this chunk
    for (int i = 0; i < chunk; i++) {
        int idx = base + i;
        if (idx < NN) {
            rowptr[idx] = run;
            cursor[idx] = run;
            run += cnt[idx];
        }
    }
    if (tid == T - 1) rowptr[NN] = run;
}

__global__ void k_fill(const int* __restrict__ ei, const float* __restrict__ nrm,
                       int* __restrict__ cursor, int* __restrict__ csrc,
                       float* __restrict__ cw) {
    int e = blockIdx.x * blockDim.x + threadIdx.x;
    if (e < EE) {
        int d = ei[EE + e];
        int pos = atomicAdd(&cursor[d], 1);
        csrc[pos] = ei[e];
        cw[pos]   = nrm[e];
    }
}

// ---------------- SGEMM: C[M,128] = A[M,K] @ B[K,128] (+bias) ---------------
// 128x128 block tile, 256 threads, 8x8 per thread, BK=16, double-buffered smem.
__global__ __launch_bounds__(256) void k_sgemm(
    const float* __restrict__ A, int lda,
    const float* __restrict__ B,
    const float* __restrict__ bias, float* __restrict__ C,
    int M, int K, int ldc)
{
    __shared__ float As[2][16][128];
    __shared__ float Bs[2][16][128];

    const int block_row = blockIdx.x * 128;
    const int tid = threadIdx.x;
    const int tr = (tid / 16) * 8;
    const int tc = (tid % 16) * 8;

    // per-thread load coordinates (A: 2 float4, B: 2 float4 per tile)
    int ar[2], ac[2], br[2], bc[2];
#pragma unroll
    for (int l = 0; l < 2; l++) {
        int v = tid + l * 256;
        ar[l] = v >> 2;           ac[l] = (v & 3) * 4;
        br[l] = v >> 5;           bc[l] = (v & 31) * 4;
    }

    float acc[8][8];
#pragma unroll
    for (int i = 0; i < 8; i++)
#pragma unroll
        for (int j = 0; j < 8; j++) acc[i][j] = 0.0f;

    const int nt = K / 16;

    auto fetchA = [&](int t, int l) -> float4 {
        int grow = block_row + ar[l];
        if (grow < M) return *(const float4*)&A[(size_t)grow * lda + t * 16 + ac[l]];
        return make_float4(0.f, 0.f, 0.f, 0.f);
    };
    auto fetchB = [&](int t, int l) -> float4 {
        return *(const float4*)&B[(size_t)(t * 16 + br[l]) * 128 + bc[l]];
    };
    auto store = [&](int buf, float4 av0, float4 av1, float4 bv0, float4 bv1) {
        float4 av[2] = {av0, av1};
        float4 bv[2] = {bv0, bv1};
#pragma unroll
        for (int l = 0; l < 2; l++) {
            As[buf][ac[l] + 0][ar[l]] = av[l].x;
            As[buf][ac[l] + 1][ar[l]] = av[l].y;
            As[buf][ac[l] + 2][ar[l]] = av[l].z;
            As[buf][ac[l] + 3][ar[l]] = av[l].w;
            *(float4*)&Bs[buf][br[l]][bc[l]] = bv[l];
        }
    };

    // preload tile 0
    store(0, fetchA(0, 0), fetchA(0, 1), fetchB(0, 0), fetchB(0, 1));
    __syncthreads();

    for (int t = 0; t < nt; t++) {
        float4 pa0, pa1, pb0, pb1;
        if (t + 1 < nt) {
            pa0 = fetchA(t + 1, 0); pa1 = fetchA(t + 1, 1);
            pb0 = fetchB(t + 1, 0); pb1 = fetchB(t + 1, 1);
        }
        int cur = t & 1;
#pragma unroll
        for (int kk = 0; kk < 16; kk++) {
            float a[8], b[8];
#pragma unroll
            for (int i = 0; i < 8; i++) a[i] = As[cur][kk][tr + i];
#pragma unroll
            for (int j = 0; j < 8; j++) b[j] = Bs[cur][kk][tc + j];
#pragma unroll
            for (int i = 0; i < 8; i++)
#pragma unroll
                for (int j = 0; j < 8; j++) acc[i][j] += a[i] * b[j];
        }
        if (t + 1 < nt) {
            __syncthreads();
            store((t + 1) & 1, pa0, pa1, pb0, pb1);
            __syncthreads();
        }
    }

#pragma unroll
    for (int i = 0; i < 8; i++) {
        int grow = block_row + tr + i;
        if (grow >= M) break;
#pragma unroll
        for (int j = 0; j < 8; j += 4) {
            float4 v;
            v.x = acc[i][j + 0];
            v.y = acc[i][j + 1];
            v.z = acc[i][j + 2];
            v.w = acc[i][j + 3];
            if (bias) {
                v.x += bias[tc + j + 0];
                v.y += bias[tc + j + 1];
                v.z += bias[tc + j + 2];
                v.w += bias[tc + j + 3];
            }
            *(float4*)&C[(size_t)grow * ldc + tc + j] = v;
        }
    }
}

// ---------------- CSR aggregation: out[d] = sum_e w*hw[src] + hw[d]/deg + b --
// warp per node, float4 per lane (128 features)
__global__ __launch_bounds__(256) void k_aggr(
    const int* __restrict__ rowptr, const int* __restrict__ csrc,
    const float* __restrict__ cw, const float4* __restrict__ hw,
    const float* __restrict__ deg, const float* __restrict__ bias,
    float4* __restrict__ out, int ldo4)
{
    int node = (blockIdx.x * blockDim.x + threadIdx.x) >> 5;
    if (node >= NN) return;
    int lane = threadIdx.x & 31;

    float sn = 1.0f / deg[node];               // dinv^2 self-loop norm
    float4 acc = hw[(size_t)node * 32 + lane];
    float4 bb  = ((const float4*)bias)[lane];
    acc.x = acc.x * sn + bb.x;
    acc.y = acc.y * sn + bb.y;
    acc.z = acc.z * sn + bb.z;
    acc.w = acc.w * sn + bb.w;

    int e  = rowptr[node];
    int e1 = rowptr[node + 1];
    // unroll-by-2 for memory-level parallelism
    for (; e + 1 < e1; e += 2) {
        int   s0 = __ldg(&csrc[e]),     s1 = __ldg(&csrc[e + 1]);
        float w0 = __ldg(&cw[e]),       w1 = __ldg(&cw[e + 1]);
        float4 v0 = hw[(size_t)s0 * 32 + lane];
        float4 v1 = hw[(size_t)s1 * 32 + lane];
        acc.x += w0 * v0.x + w1 * v1.x;
        acc.y += w0 * v0.y + w1 * v1.y;
        acc.z += w0 * v0.z + w1 * v1.z;
        acc.w += w0 * v0.w + w1 * v1.w;
    }
    if (e < e1) {
        int   s0 = __ldg(&csrc[e]);
        float w0 = __ldg(&cw[e]);
        float4 v0 = hw[(size_t)s0 * 32 + lane];
        acc.x += w0 * v0.x;
        acc.y += w0 * v0.y;
        acc.z += w0 * v0.z;
        acc.w += w0 * v0.w;
    }
    out[(size_t)node * ldo4 + lane] = acc;
}

// ---------------- final: out = cat @ W_out + b_out (tiled) ------------------
// 128 rows x 40 cols per block, 256 threads, 4x5 per thread, BK=16
__global__ __launch_bounds__(256) void k_out(
    const float* __restrict__ cat, const float* __restrict__ W,
    const float* __restrict__ b, float* __restrict__ out)
{
    __shared__ float As[16][128];
    __shared__ float Ws[16][40];

    const int block_row = blockIdx.x * 128;
    const int tid = threadIdx.x;
    const int r0 = (tid / 8) * 4;     // 32 row-groups of 4
    const int c0 = (tid % 8) * 5;     // 8 col-groups of 5

    float acc[4][5];
#pragma unroll
    for (int i = 0; i < 4; i++)
#pragma unroll
        for (int j = 0; j < 5; j++) acc[i][j] = 0.0f;

    for (int k0 = 0; k0 < NCAT; k0 += 16) {
        // A tile: 128 x 16 = 512 float4
#pragma unroll
        for (int l = 0; l < 2; l++) {
            int v  = tid + l * 256;
            int r  = v >> 2;
            int c4 = (v & 3) * 4;
            float4 av = make_float4(0.f, 0.f, 0.f, 0.f);
            int grow = block_row + r;
            if (grow < NN)
                av = *(const float4*)&cat[(size_t)grow * NCAT + k0 + c4];
            As[c4 + 0][r] = av.x;
            As[c4 + 1][r] = av.y;
            As[c4 + 2][r] = av.z;
            As[c4 + 3][r] = av.w;
        }
        // W tile: 16 x 40 = 640 floats
#pragma unroll
        for (int l = 0; l < 3; l++) {
            int idx = tid + l * 256;
            if (idx < 16 * 40) {
                int r = idx / 40, c = idx % 40;
                Ws[r][c] = W[(size_t)(k0 + r) * CC + c];
            }
        }
        __syncthreads();

#pragma unroll
        for (int kk = 0; kk < 16; kk++) {
            float a[4], w[5];
#pragma unroll
            for (int i = 0; i < 4; i++) a[i] = As[kk][r0 + i];
#pragma unroll
            for (int j = 0; j < 5; j++) w[j] = Ws[kk][c0 + j];
#pragma unroll
            for (int i = 0; i < 4; i++)
#pragma unroll
                for (int j = 0; j < 5; j++) acc[i][j] += a[i] * w[j];
        }
        __syncthreads();
    }

#pragma unroll
    for (int i = 0; i < 4; i++) {
        int grow = block_row + r0 + i;
        if (grow >= NN) break;
#pragma unroll
        for (int j = 0; j < 5; j++)
            out[(size_t)grow * CC + c0 + j] = acc[i][j] + b[c0 + j];
    }
}

// ---------------- launch -----------------------------------------------------
extern "C" void kernel_launch(void* const* d_in, const int* in_sizes, int n_in,
                              void* d_out, int out_size) {
    const float* x     = (const float*)d_in[0];
    const int*   ei    = (const int*)  d_in[1];
    const float* ew    = (const float*)d_in[2];
    const float* W_in  = (const float*)d_in[3];
    const float* b_in  = (const float*)d_in[4];
    const float* W_gcn = (const float*)d_in[5];
    const float* b_gcn = (const float*)d_in[6];
    const float* W_out = (const float*)d_in[7];
    const float* b_out = (const float*)d_in[8];
    float* out = (float*)d_out;

    float *deg, *nrm, *hw, *t0, *t1, *cat, *cw;
    int *cnt, *rowptr, *cursor, *csrc;
    cudaGetSymbolAddress((void**)&deg,    g_deg);
    cudaGetSymbolAddress((void**)&nrm,    g_norm);
    cudaGetSymbolAddress((void**)&hw,     g_hw);
    cudaGetSymbolAddress((void**)&t0,     g_t0);
    cudaGetSymbolAddress((void**)&t1,     g_t1);
    cudaGetSymbolAddress((void**)&cat,    g_cat);
    cudaGetSymbolAddress((void**)&cnt,    g_cnt);
    cudaGetSymbolAddress((void**)&rowptr, g_rowptr);
    cudaGetSymbolAddress((void**)&cursor, g_cursor);
    cudaGetSymbolAddress((void**)&csrc,   g_csrc);
    cudaGetSymbolAddress((void**)&cw,     g_cw);

    // degree + norm + CSR
    k_deg_init<<<(NN + 255) / 256, 256>>>(deg, cnt);
    k_deg_acc <<<(EE + 255) / 256, 256>>>(ei, ew, deg, cnt);
    k_norm    <<<(EE + 255) / 256, 256>>>(ei, ew, deg, nrm);
    k_scan    <<<1, 1024>>>(cnt, rowptr, cursor);
    k_fill    <<<(EE + 255) / 256, 256>>>(ei, nrm, cursor, csrc, cw);

    // h = x @ W_in + b_in, written directly into cat[:, 0:128]
    k_sgemm<<<(NN + 127) / 128, 256>>>(x, FF, W_in, b_in, cat, NN, FF, NCAT);

    // one GCN conv: dst = aggr(norm * (in@Wk)) + self + bias
    auto gcn = [&](const float* in, int lda, int k, float* dst, int ldo) {
        k_sgemm<<<(NN + 127) / 128, 256>>>(in, lda, W_gcn + (size_t)k * HH * HH,
                                           nullptr, hw, NN, HH, HH);
        k_aggr <<<(NN * 32 + 255) / 256, 256>>>(rowptr, csrc, cw,
                                                (const float4*)hw, deg,
                                                b_gcn + (size_t)k * HH,
                                                (float4*)dst, ldo / 4);
    };

    const float* h = cat;                       // stride NCAT

    gcn(h,  NCAT, 0, cat + 1 * HH, NCAT);       // chain 1

    gcn(h,  NCAT, 1, t0, HH);                   // chain 2
    gcn(t0, HH,   2, cat + 2 * HH, NCAT);

    gcn(h,  NCAT, 3, t0, HH);                   // chain 3
    gcn(t0, HH,   4, t1, HH);
    gcn(t1, HH,   5, cat + 3 * HH, NCAT);

    gcn(h,  NCAT, 6, t0, HH);                   // chain 4
    gcn(t0, HH,   7, t1, HH);
    gcn(t1, HH,   8, t0, HH);
    gcn(t0, HH,   9, cat + 4 * HH, NCAT);

    // out = cat @ W_out + b_out
    k_out<<<(NN + 127) / 128, 256>>>(cat, W_out, b_out, out);
}

// round 3
// speedup vs baseline: 1.8586x; 1.1302x over previous
#include <cuda_runtime.h>
#include <cstdint>

#define NN 50000
#define EE 800000
#define FF 512
#define HH 128
#define CC 40
#define NCAT 640   // (1 + 4) * 128
#define NB_SCAN 196  // ceil(NN / 256)

// ---------------- scratch (device globals; no allocation allowed) -----------
static __device__ __align__(256) float g_deg[NN];
static __device__ __align__(256) float g_hw[NN * HH];
static __device__ __align__(256) float g_t0[NN * HH];
static __device__ __align__(256) float g_t1[NN * HH];
static __device__ __align__(256) float g_cat[(size_t)NN * NCAT];
// CSR scratch
static __device__ __align__(256) int   g_cnt[NN];
static __device__ __align__(256) int   g_rowptr[NN + 1];
static __device__ __align__(256) int   g_cursor[NN];
static __device__ __align__(256) int   g_csrc[EE];
static __device__ __align__(256) float g_cw[EE];
static __device__ __align__(256) int   g_bsum[256];
static __device__ __align__(256) int   g_boff[256];

// ---------------- degree / CSR build ----------------------------------------
__global__ void k_deg_init(float* __restrict__ deg, int* __restrict__ cnt) {
    int i = blockIdx.x * blockDim.x + threadIdx.x;
    if (i < NN) { deg[i] = 1.0f; cnt[i] = 0; }     // self-loop weight
}

__global__ void k_deg_acc(const int* __restrict__ ei, const float* __restrict__ ew,
                          float* __restrict__ deg, int* __restrict__ cnt) {
    int e = blockIdx.x * blockDim.x + threadIdx.x;
    if (e < EE) {
        int d = ei[EE + e];
        atomicAdd(&deg[d], ew[e]);
        atomicAdd(&cnt[d], 1);
    }
}

__global__ void k_scan1(const int* __restrict__ cnt, int* __restrict__ bsum) {
    __shared__ int s[256];
    int i = blockIdx.x * 256 + threadIdx.x;
    s[threadIdx.x] = (i < NN) ? cnt[i] : 0;
    __syncthreads();
    for (int off = 128; off > 0; off >>= 1) {
        if (threadIdx.x < off) s[threadIdx.x] += s[threadIdx.x + off];
        __syncthreads();
    }
    if (threadIdx.x == 0) bsum[blockIdx.x] = s[0];
}

__global__ void k_scan2(const int* __restrict__ bsum, int* __restrict__ boff,
                        int* __restrict__ rowptr) {
    __shared__ int s[256];
    int t = threadIdx.x;
    int v = (t < NB_SCAN) ? bsum[t] : 0;
    s[t] = v;
    __syncthreads();
    for (int off = 1; off < 256; off <<= 1) {
        int u = (t >= off) ? s[t - off] : 0;
        __syncthreads();
        s[t] += u;
        __syncthreads();
    }
    boff[t] = s[t] - v;                  // exclusive
    if (t == 255) rowptr[NN] = s[255];
}

__global__ void k_scan3(const int* __restrict__ cnt, const int* __restrict__ boff,
                        int* __restrict__ rowptr, int* __restrict__ cursor) {
    __shared__ int s[256];
    int i = blockIdx.x * 256 + threadIdx.x;
    int t = threadIdx.x;
    int v = (i < NN) ? cnt[i] : 0;
    s[t] = v;
    __syncthreads();
    for (int off = 1; off < 256; off <<= 1) {
        int u = (t >= off) ? s[t - off] : 0;
        __syncthreads();
        s[t] += u;
        __syncthreads();
    }
    int ex = boff[blockIdx.x] + s[t] - v;
    if (i < NN) { rowptr[i] = ex; cursor[i] = ex; }
}

__global__ void k_fill(const int* __restrict__ ei, const float* __restrict__ ew,
                       const float* __restrict__ deg, int* __restrict__ cursor,
                       int* __restrict__ csrc, float* __restrict__ cw) {
    int e = blockIdx.x * blockDim.x + threadIdx.x;
    if (e < EE) {
        int s = ei[e], d = ei[EE + e];
        int pos = atomicAdd(&cursor[d], 1);
        csrc[pos] = s;
        cw[pos]   = ew[e] * rsqrtf(deg[s]) * rsqrtf(deg[d]);
    }
}

// ---------------- 3xTF32 tensor-core GEMM -----------------------------------
// C[M,128] = A[M,K] @ B[K,128] (+bias), error ~2^-22 via hi/lo split.
// Block 128x128, 256 threads (8 warps, 4x2), warp tile 32x64, mma m16n8k8.
__device__ __forceinline__ uint32_t f2tf32(float x) {
    uint32_t r;
    asm("cvt.rna.tf32.f32 %0, %1;" : "=r"(r) : "f"(x));
    return r;
}

__device__ __forceinline__ void mma_tf32(float c[4], const uint32_t a[4],
                                         uint32_t b0, uint32_t b1) {
    asm volatile(
        "mma.sync.aligned.m16n8k8.row.col.f32.tf32.tf32.f32 "
        "{%0,%1,%2,%3}, {%4,%5,%6,%7}, {%8,%9}, {%0,%1,%2,%3};"
        : "+f"(c[0]), "+f"(c[1]), "+f"(c[2]), "+f"(c[3])
        : "r"(a[0]), "r"(a[1]), "r"(a[2]), "r"(a[3]), "r"(b0), "r"(b1));
}

#define BK 16
#define LDSM 132   // 128 + 4 pad

__global__ __launch_bounds__(256) void k_mma(
    const float* __restrict__ A, int lda,
    const float* __restrict__ B,
    const float* __restrict__ bias, float* __restrict__ C,
    int M, int K, int ldc)
{
    __shared__ uint32_t Ah[BK * LDSM], Al[BK * LDSM];
    __shared__ uint32_t Bh[BK * LDSM], Bl[BK * LDSM];

    const int tid  = threadIdx.x;
    const int wid  = tid >> 5;
    const int lane = tid & 31;
    const int g    = lane >> 2;         // 0..7
    const int tg   = lane & 3;          // 0..3
    const int wm   = (wid & 3) * 32;    // warp row offset in tile
    const int wn   = (wid >> 2) * 64;   // warp col offset in tile
    const int brow = blockIdx.x * 128;

    float acc[2][8][4];
#pragma unroll
    for (int mt = 0; mt < 2; mt++)
#pragma unroll
        for (int nt = 0; nt < 8; nt++)
#pragma unroll
            for (int j = 0; j < 4; j++) acc[mt][nt][j] = 0.0f;

    for (int kc = 0; kc < K; kc += BK) {
        // load A tile 128x16 (2 float4 per thread), split hi/lo, store [k][m]
#pragma unroll
        for (int l = 0; l < 2; l++) {
            int v  = tid + l * 256;
            int r  = v >> 2;
            int c4 = (v & 3) * 4;
            int grow = brow + r;
            float4 av = make_float4(0.f, 0.f, 0.f, 0.f);
            if (grow < M) av = *(const float4*)&A[(size_t)grow * lda + kc + c4];
            float aa[4] = {av.x, av.y, av.z, av.w};
#pragma unroll
            for (int j = 0; j < 4; j++) {
                uint32_t hb = f2tf32(aa[j]);
                float lo = aa[j] - __uint_as_float(hb);
                Ah[(c4 + j) * LDSM + r] = hb;
                Al[(c4 + j) * LDSM + r] = f2tf32(lo);
            }
        }
        // load B tile 16x128, split hi/lo, store [k][n]
#pragma unroll
        for (int l = 0; l < 2; l++) {
            int v  = tid + l * 256;
            int r  = v >> 5;
            int c4 = (v & 31) * 4;
            float4 bv = *(const float4*)&B[(size_t)(kc + r) * 128 + c4];
            float bb[4] = {bv.x, bv.y, bv.z, bv.w};
#pragma unroll
            for (int j = 0; j < 4; j++) {
                uint32_t hb = f2tf32(bb[j]);
                float lo = bb[j] - __uint_as_float(hb);
                Bh[r * LDSM + c4 + j] = hb;
                Bl[r * LDSM + c4 + j] = f2tf32(lo);
            }
        }
        __syncthreads();

#pragma unroll
        for (int ks = 0; ks < 2; ks++) {
            int k0 = ks * 8;
            uint32_t ahf[2][4], alf[2][4];
#pragma unroll
            for (int mt = 0; mt < 2; mt++) {
                int m0 = wm + mt * 16;
                ahf[mt][0] = Ah[(k0 + tg) * LDSM + m0 + g];
                ahf[mt][1] = Ah[(k0 + tg) * LDSM + m0 + g + 8];
                ahf[mt][2] = Ah[(k0 + tg + 4) * LDSM + m0 + g];
                ahf[mt][3] = Ah[(k0 + tg + 4) * LDSM + m0 + g + 8];
                alf[mt][0] = Al[(k0 + tg) * LDSM + m0 + g];
                alf[mt][1] = Al[(k0 + tg) * LDSM + m0 + g + 8];
                alf[mt][2] = Al[(k0 + tg + 4) * LDSM + m0 + g];
                alf[mt][3] = Al[(k0 + tg + 4) * LDSM + m0 + g + 8];
            }
#pragma unroll
            for (int nt = 0; nt < 8; nt++) {
                int n0 = wn + nt * 8;
                uint32_t b0h = Bh[(k0 + tg) * LDSM + n0 + g];
                uint32_t b1h = Bh[(k0 + tg + 4) * LDSM + n0 + g];
                uint32_t b0l = Bl[(k0 + tg) * LDSM + n0 + g];
                uint32_t b1l = Bl[(k0 + tg + 4) * LDSM + n0 + g];
#pragma unroll
                for (int mt = 0; mt < 2; mt++) {
                    mma_tf32(acc[mt][nt], ahf[mt], b0h, b1h);   // hi*hi
                    mma_tf32(acc[mt][nt], alf[mt], b0h, b1h);   // lo*hi
                    mma_tf32(acc[mt][nt], ahf[mt], b0l, b1l);   // hi*lo
                }
            }
        }
        __syncthreads();
    }

    // epilogue
#pragma unroll
    for (int mt = 0; mt < 2; mt++) {
        int r0 = brow + wm + mt * 16 + g;
        int r1 = r0 + 8;
#pragma unroll
        for (int nt = 0; nt < 8; nt++) {
            int col = wn + nt * 8 + tg * 2;
            float2 v0 = make_float2(acc[mt][nt][0], acc[mt][nt][1]);
            float2 v1 = make_float2(acc[mt][nt][2], acc[mt][nt][3]);
            if (bias) {
                float b0 = bias[col], b1 = bias[col + 1];
                v0.x += b0; v0.y += b1;
                v1.x += b0; v1.y += b1;
            }
            if (r0 < M) *(float2*)&C[(size_t)r0 * ldc + col] = v0;
            if (r1 < M) *(float2*)&C[(size_t)r1 * ldc + col] = v1;
        }
    }
}

// ---------------- CSR aggregation: out[d] = sum_e w*hw[src] + hw[d]/deg + b --
__global__ __launch_bounds__(256) void k_aggr(
    const int* __restrict__ rowptr, const int* __restrict__ csrc,
    const float* __restrict__ cw, const float4* __restrict__ hw,
    const float* __restrict__ deg, const float* __restrict__ bias,
    float4* __restrict__ out, int ldo4)
{
    int node = (blockIdx.x * blockDim.x + threadIdx.x) >> 5;
    if (node >= NN) return;
    int lane = threadIdx.x & 31;

    float sn = 1.0f / deg[node];
    float4 acc = hw[(size_t)node * 32 + lane];
    float4 bb  = ((const float4*)bias)[lane];
    acc.x = acc.x * sn + bb.x;
    acc.y = acc.y * sn + bb.y;
    acc.z = acc.z * sn + bb.z;
    acc.w = acc.w * sn + bb.w;

    int e  = rowptr[node];
    int e1 = rowptr[node + 1];
    for (; e + 1 < e1; e += 2) {
        int   s0 = __ldg(&csrc[e]),     s1 = __ldg(&csrc[e + 1]);
        float w0 = __ldg(&cw[e]),       w1 = __ldg(&cw[e + 1]);
        float4 v0 = hw[(size_t)s0 * 32 + lane];
        float4 v1 = hw[(size_t)s1 * 32 + lane];
        acc.x += w0 * v0.x + w1 * v1.x;
        acc.y += w0 * v0.y + w1 * v1.y;
        acc.z += w0 * v0.z + w1 * v1.z;
        acc.w += w0 * v0.w + w1 * v1.w;
    }
    if (e < e1) {
        int   s0 = __ldg(&csrc[e]);
        float w0 = __ldg(&cw[e]);
        float4 v0 = hw[(size_t)s0 * 32 + lane];
        acc.x += w0 * v0.x;
        acc.y += w0 * v0.y;
        acc.z += w0 * v0.z;
        acc.w += w0 * v0.w;
    }
    out[(size_t)node * ldo4 + lane] = acc;
}

// ---------------- final: out = cat @ W_out + b_out (tiled) ------------------
__global__ __launch_bounds__(256) void k_out(
    const float* __restrict__ cat, const float* __restrict__ W,
    const float* __restrict__ b, float* __restrict__ out)
{
    __shared__ float As[16][128];
    __shared__ float Ws[16][40];

    const int block_row = blockIdx.x * 128;
    const int tid = threadIdx.x;
    const int r0 = (tid / 8) * 4;
    const int c0 = (tid % 8) * 5;

    float acc[4][5];
#pragma unroll
    for (int i = 0; i < 4; i++)
#pragma unroll
        for (int j = 0; j < 5; j++) acc[i][j] = 0.0f;

    for (int k0 = 0; k0 < NCAT; k0 += 16) {
#pragma unroll
        for (int l = 0; l < 2; l++) {
            int v  = tid + l * 256;
            int r  = v >> 2;
            int c4 = (v & 3) * 4;
            float4 av = make_float4(0.f, 0.f, 0.f, 0.f);
            int grow = block_row + r;
            if (grow < NN)
                av = *(const float4*)&cat[(size_t)grow * NCAT + k0 + c4];
            As[c4 + 0][r] = av.x;
            As[c4 + 1][r] = av.y;
            As[c4 + 2][r] = av.z;
            As[c4 + 3][r] = av.w;
        }
#pragma unroll
        for (int l = 0; l < 3; l++) {
            int idx = tid + l * 256;
            if (idx < 16 * 40) {
                int r = idx / 40, c = idx % 40;
                Ws[r][c] = W[(size_t)(k0 + r) * CC + c];
            }
        }
        __syncthreads();

#pragma unroll
        for (int kk = 0; kk < 16; kk++) {
            float a[4], w[5];
#pragma unroll
            for (int i = 0; i < 4; i++) a[i] = As[kk][r0 + i];
#pragma unroll
            for (int j = 0; j < 5; j++) w[j] = Ws[kk][c0 + j];
#pragma unroll
            for (int i = 0; i < 4; i++)
#pragma unroll
                for (int j = 0; j < 5; j++) acc[i][j] += a[i] * w[j];
        }
        __syncthreads();
    }

#pragma unroll
    for (int i = 0; i < 4; i++) {
        int grow = block_row + r0 + i;
        if (grow >= NN) break;
#pragma unroll
        for (int j = 0; j < 5; j++)
            out[(size_t)grow * CC + c0 + j] = acc[i][j] + b[c0 + j];
    }
}

// ---------------- launch -----------------------------------------------------
extern "C" void kernel_launch(void* const* d_in, const int* in_sizes, int n_in,
                              void* d_out, int out_size) {
    const float* x     = (const float*)d_in[0];
    const int*   ei    = (const int*)  d_in[1];
    const float* ew    = (const float*)d_in[2];
    const float* W_in  = (const float*)d_in[3];
    const float* b_in  = (const float*)d_in[4];
    const float* W_gcn = (const float*)d_in[5];
    const float* b_gcn = (const float*)d_in[6];
    const float* W_out = (const float*)d_in[7];
    const float* b_out = (const float*)d_in[8];
    float* out = (float*)d_out;

    float *deg, *hw, *t0, *t1, *cat, *cw;
    int *cnt, *rowptr, *cursor, *csrc, *bsum, *boff;
    cudaGetSymbolAddress((void**)&deg,    g_deg);
    cudaGetSymbolAddress((void**)&hw,     g_hw);
    cudaGetSymbolAddress((void**)&t0,     g_t0);
    cudaGetSymbolAddress((void**)&t1,     g_t1);
    cudaGetSymbolAddress((void**)&cat,    g_cat);
    cudaGetSymbolAddress((void**)&cnt,    g_cnt);
    cudaGetSymbolAddress((void**)&rowptr, g_rowptr);
    cudaGetSymbolAddress((void**)&cursor, g_cursor);
    cudaGetSymbolAddress((void**)&csrc,   g_csrc);
    cudaGetSymbolAddress((void**)&cw,     g_cw);
    cudaGetSymbolAddress((void**)&bsum,   g_bsum);
    cudaGetSymbolAddress((void**)&boff,   g_boff);

    // degree + CSR (parallel scan)
    k_deg_init<<<(NN + 255) / 256, 256>>>(deg, cnt);
    k_deg_acc <<<(EE + 255) / 256, 256>>>(ei, ew, deg, cnt);
    k_scan1   <<<NB_SCAN, 256>>>(cnt, bsum);
    k_scan2   <<<1, 256>>>(bsum, boff, rowptr);
    k_scan3   <<<NB_SCAN, 256>>>(cnt, boff, rowptr, cursor);
    k_fill    <<<(EE + 255) / 256, 256>>>(ei, ew, deg, cursor, csrc, cw);

    // h = x @ W_in + b_in, written directly into cat[:, 0:128]
    k_mma<<<(NN + 127) / 128, 256>>>(x, FF, W_in, b_in, cat, NN, FF, NCAT);

    // one GCN conv: dst = aggr(norm * (in@Wk)) + self + bias
    auto gcn = [&](const float* in, int lda, int k, float* dst, int ldo) {
        k_mma <<<(NN + 127) / 128, 256>>>(in, lda, W_gcn + (size_t)k * HH * HH,
                                          nullptr, hw, NN, HH, HH);
        k_aggr<<<(NN * 32 + 255) / 256, 256>>>(rowptr, csrc, cw,
                                               (const float4*)hw, deg,
                                               b_gcn + (size_t)k * HH,
                                               (float4*)dst, ldo / 4);
    };

    const float* h = cat;                       // stride NCAT

    gcn(h,  NCAT, 0, cat + 1 * HH, NCAT);       // chain 1

    gcn(h,  NCAT, 1, t0, HH);                   // chain 2
    gcn(t0, HH,   2, cat + 2 * HH, NCAT);

    gcn(h,  NCAT, 3, t0, HH);                   // chain 3
    gcn(t0, HH,   4, t1, HH);
    gcn(t1, HH,   5, cat + 3 * HH, NCAT);

    gcn(h,  NCAT, 6, t0, HH);                   // chain 4
    gcn(t0, HH,   7, t1, HH);
    gcn(t1, HH,   8, t0, HH);
    gcn(t0, HH,   9, cat + 4 * HH, NCAT);

    // out = cat @ W_out + b_out
    k_out<<<(NN + 127) / 128, 256>>>(cat, W_out, b_out, out);
}

// round 5
// speedup vs baseline: 2.1372x; 1.1499x over previous
#include <cuda_runtime.h>
#include <cuda_fp16.h>
#include <cstdint>

#define NN 50000
#define EE 800000
#define FF 512
#define HH 128
#define CC 40
#define NCAT 640     // (1 + 4) * 128
#define NB_SCAN 196  // ceil(NN / 256)
#define WMAIN (FF * HH + 10 * HH * HH)   // 229376 (W_in + 10x W_gcn)
#define WOUTN (NCAT * CC)                // 25600

// ---------------- scratch (device globals; no allocation allowed) -----------
static __device__ __align__(256) float    g_deg[NN];
static __device__ __align__(256) __half2  g_hwh[NN * 64];   // fp16 hw (128 feats)
static __device__ __align__(256) float    g_t0[NN * HH];
static __device__ __align__(256) float    g_t1[NN * HH];
static __device__ __align__(256) float    g_cat[(size_t)NN * NCAT];
// pre-split weights (tf32 hi/lo)
static __device__ __align__(256) uint32_t g_bh[WMAIN], g_bl[WMAIN];
static __device__ __align__(256) uint32_t g_woh[WOUTN], g_wol[WOUTN];
// CSR scratch
static __device__ __align__(256) int   g_cnt[NN];
static __device__ __align__(256) int   g_rowptr[NN + 1];
static __device__ __align__(256) int   g_cursor[NN];
static __device__ __align__(256) int   g_csrc[EE];
static __device__ __align__(256) float g_cw[EE];
static __device__ __align__(256) int   g_bsum[256];
static __device__ __align__(256) int   g_boff[256];

__device__ __forceinline__ uint32_t f2tf32(float x) {
    uint32_t r;
    asm("cvt.rna.tf32.f32 %0, %1;" : "=r"(r) : "f"(x));
    return r;
}

// ---------------- weight pre-split ------------------------------------------
__global__ void k_wsplit(const float* __restrict__ W_in,
                         const float* __restrict__ W_gcn,
                         const float* __restrict__ W_out,
                         uint32_t* __restrict__ bh, uint32_t* __restrict__ bl,
                         uint32_t* __restrict__ woh, uint32_t* __restrict__ wol) {
    int i = blockIdx.x * blockDim.x + threadIdx.x;
    if (i < WMAIN) {
        float v = (i < FF * HH) ? W_in[i] : W_gcn[i - FF * HH];
        uint32_t h = f2tf32(v);
        bh[i] = h;
        bl[i] = f2tf32(v - __uint_as_float(h));
    } else if (i < WMAIN + WOUTN) {
        int j = i - WMAIN;
        float v = W_out[j];
        uint32_t h = f2tf32(v);
        woh[j] = h;
        wol[j] = f2tf32(v - __uint_as_float(h));
    }
}

// ---------------- degree / CSR build ----------------------------------------
__global__ void k_deg_init(float* __restrict__ deg, int* __restrict__ cnt) {
    int i = blockIdx.x * blockDim.x + threadIdx.x;
    if (i < NN) { deg[i] = 1.0f; cnt[i] = 0; }
}

__global__ void k_deg_acc(const int* __restrict__ ei, const float* __restrict__ ew,
                          float* __restrict__ deg, int* __restrict__ cnt) {
    int e = blockIdx.x * blockDim.x + threadIdx.x;
    if (e < EE) {
        int d = ei[EE + e];
        atomicAdd(&deg[d], ew[e]);
        atomicAdd(&cnt[d], 1);
    }
}

__global__ void k_scan1(const int* __restrict__ cnt, int* __restrict__ bsum) {
    __shared__ int s[256];
    int i = blockIdx.x * 256 + threadIdx.x;
    s[threadIdx.x] = (i < NN) ? cnt[i] : 0;
    __syncthreads();
    for (int off = 128; off > 0; off >>= 1) {
        if (threadIdx.x < off) s[threadIdx.x] += s[threadIdx.x + off];
        __syncthreads();
    }
    if (threadIdx.x == 0) bsum[blockIdx.x] = s[0];
}

__global__ void k_scan2(const int* __restrict__ bsum, int* __restrict__ boff,
                        int* __restrict__ rowptr) {
    __shared__ int s[256];
    int t = threadIdx.x;
    int v = (t < NB_SCAN) ? bsum[t] : 0;
    s[t] = v;
    __syncthreads();
    for (int off = 1; off < 256; off <<= 1) {
        int u = (t >= off) ? s[t - off] : 0;
        __syncthreads();
        s[t] += u;
        __syncthreads();
    }
    boff[t] = s[t] - v;
    if (t == 255) rowptr[NN] = s[255];
}

__global__ void k_scan3(const int* __restrict__ cnt, const int* __restrict__ boff,
                        int* __restrict__ rowptr, int* __restrict__ cursor) {
    __shared__ int s[256];
    int i = blockIdx.x * 256 + threadIdx.x;
    int t = threadIdx.x;
    int v = (i < NN) ? cnt[i] : 0;
    s[t] = v;
    __syncthreads();
    for (int off = 1; off < 256; off <<= 1) {
        int u = (t >= off) ? s[t - off] : 0;
        __syncthreads();
        s[t] += u;
        __syncthreads();
    }
    int ex = boff[blockIdx.x] + s[t] - v;
    if (i < NN) { rowptr[i] = ex; cursor[i] = ex; }
}

__global__ void k_fill(const int* __restrict__ ei, const float* __restrict__ ew,
                       const float* __restrict__ deg, int* __restrict__ cursor,
                       int* __restrict__ csrc, float* __restrict__ cw) {
    int e = blockIdx.x * blockDim.x + threadIdx.x;
    if (e < EE) {
        int s = ei[e], d = ei[EE + e];
        int pos = atomicAdd(&cursor[d], 1);
        csrc[pos] = s;
        cw[pos]   = ew[e] * rsqrtf(deg[s]) * rsqrtf(deg[d]);
    }
}

// ---------------- 3xTF32 tensor-core GEMM -----------------------------------
// C[M,128] = A[M,K] @ B[K,128] (+bias). B pre-split in global (Bh_g/Bl_g).
// Block 128x128, 256 threads (8 warps 4x2), warp tile 32x64, mma m16n8k8.
// Register-prefetch double buffering. Output: fp32 C or fp16 hout.
__device__ __forceinline__ void mma_tf32(float c[4], const uint32_t a[4],
                                         uint32_t b0, uint32_t b1) {
    asm volatile(
        "mma.sync.aligned.m16n8k8.row.col.f32.tf32.tf32.f32 "
        "{%0,%1,%2,%3}, {%4,%5,%6,%7}, {%8,%9}, {%0,%1,%2,%3};"
        : "+f"(c[0]), "+f"(c[1]), "+f"(c[2]), "+f"(c[3])
        : "r"(a[0]), "r"(a[1]), "r"(a[2]), "r"(a[3]), "r"(b0), "r"(b1));
}

#define BK 16
#define LDP 136   // 136 mod 32 == 8 -> conflict-free fragment loads

__global__ __launch_bounds__(256) void k_mma(
    const float* __restrict__ A, int lda,
    const uint32_t* __restrict__ Bh_g, const uint32_t* __restrict__ Bl_g,
    const float* __restrict__ bias, float* __restrict__ C, int ldc,
    __half2* __restrict__ hout, int M, int K)
{
    __shared__ uint32_t Ah[BK * LDP], Al[BK * LDP];
    __shared__ uint32_t Bh[BK * LDP], Bl[BK * LDP];

    const int tid  = threadIdx.x;
    const int wid  = tid >> 5;
    const int lane = tid & 31;
    const int g    = lane >> 2;
    const int tg   = lane & 3;
    const int wm   = (wid & 3) * 32;
    const int wn   = (wid >> 2) * 64;
    const int brow = blockIdx.x * 128;

    // load coords: A tile 128x16 (2 float4/thr), B tile 16x128 (2 uint4/thr each)
    int ar[2], ac[2], br[2], bc[2];
#pragma unroll
    for (int l = 0; l < 2; l++) {
        int v = tid + l * 256;
        ar[l] = v >> 2;  ac[l] = (v & 3) * 4;
        br[l] = v >> 5;  bc[l] = (v & 31) * 4;
    }

    float acc[2][8][4];
#pragma unroll
    for (int mt = 0; mt < 2; mt++)
#pragma unroll
        for (int nt = 0; nt < 8; nt++)
#pragma unroll
            for (int j = 0; j < 4; j++) acc[mt][nt][j] = 0.0f;

    const int nt_tiles = K / BK;

    float4 pa[2];
    uint4  pbh[2], pbl[2];

    auto fetch = [&](int t) {
#pragma unroll
        for (int l = 0; l < 2; l++) {
            int grow = brow + ar[l];
            pa[l] = make_float4(0.f, 0.f, 0.f, 0.f);
            if (grow < M)
                pa[l] = *(const float4*)&A[(size_t)grow * lda + t * BK + ac[l]];
            pbh[l] = *(const uint4*)&Bh_g[(size_t)(t * BK + br[l]) * 128 + bc[l]];
            pbl[l] = *(const uint4*)&Bl_g[(size_t)(t * BK + br[l]) * 128 + bc[l]];
        }
    };
    auto store = [&]() {
#pragma unroll
        for (int l = 0; l < 2; l++) {
            float aa[4] = {pa[l].x, pa[l].y, pa[l].z, pa[l].w};
#pragma unroll
            for (int j = 0; j < 4; j++) {
                uint32_t hb = f2tf32(aa[j]);
                Ah[(ac[l] + j) * LDP + ar[l]] = hb;
                Al[(ac[l] + j) * LDP + ar[l]] = f2tf32(aa[j] - __uint_as_float(hb));
            }
            *(uint4*)&Bh[br[l] * LDP + bc[l]] = pbh[l];
            *(uint4*)&Bl[br[l] * LDP + bc[l]] = pbl[l];
        }
    };

    fetch(0);
    store();
    __syncthreads();

    for (int t = 0; t < nt_tiles; t++) {
        if (t + 1 < nt_tiles) fetch(t + 1);

#pragma unroll
        for (int ks = 0; ks < 2; ks++) {
            int k0 = ks * 8;
            uint32_t ahf[2][4], alf[2][4];
#pragma unroll
            for (int mt = 0; mt < 2; mt++) {
                int m0 = wm + mt * 16;
                ahf[mt][0] = Ah[(k0 + tg) * LDP + m0 + g];
                ahf[mt][1] = Ah[(k0 + tg) * LDP + m0 + g + 8];
                ahf[mt][2] = Ah[(k0 + tg + 4) * LDP + m0 + g];
                ahf[mt][3] = Ah[(k0 + tg + 4) * LDP + m0 + g + 8];
                alf[mt][0] = Al[(k0 + tg) * LDP + m0 + g];
                alf[mt][1] = Al[(k0 + tg) * LDP + m0 + g + 8];
                alf[mt][2] = Al[(k0 + tg + 4) * LDP + m0 + g];
                alf[mt][3] = Al[(k0 + tg + 4) * LDP + m0 + g + 8];
            }
#pragma unroll
            for (int nt = 0; nt < 8; nt++) {
                int n0 = wn + nt * 8;
                uint32_t b0h = Bh[(k0 + tg) * LDP + n0 + g];
                uint32_t b1h = Bh[(k0 + tg + 4) * LDP + n0 + g];
                uint32_t b0l = Bl[(k0 + tg) * LDP + n0 + g];
                uint32_t b1l = Bl[(k0 + tg + 4) * LDP + n0 + g];
#pragma unroll
                for (int mt = 0; mt < 2; mt++) {
                    mma_tf32(acc[mt][nt], ahf[mt], b0h, b1h);
                    mma_tf32(acc[mt][nt], alf[mt], b0h, b1h);
                    mma_tf32(acc[mt][nt], ahf[mt], b0l, b1l);
                }
            }
        }
        if (t + 1 < nt_tiles) {
            __syncthreads();
            store();
            __syncthreads();
        }
    }

    // epilogue
#pragma unroll
    for (int mt = 0; mt < 2; mt++) {
        int r0 = brow + wm + mt * 16 + g;
        int r1 = r0 + 8;
#pragma unroll
        for (int nt = 0; nt < 8; nt++) {
            int col = wn + nt * 8 + tg * 2;
            if (hout) {
                if (r0 < M)
                    hout[(size_t)r0 * 64 + (col >> 1)] =
                        __floats2half2_rn(acc[mt][nt][0], acc[mt][nt][1]);
                if (r1 < M)
                    hout[(size_t)r1 * 64 + (col >> 1)] =
                        __floats2half2_rn(acc[mt][nt][2], acc[mt][nt][3]);
            } else {
                float2 v0 = make_float2(acc[mt][nt][0], acc[mt][nt][1]);
                float2 v1 = make_float2(acc[mt][nt][2], acc[mt][nt][3]);
                if (bias) {
                    float b0 = bias[col], b1 = bias[col + 1];
                    v0.x += b0; v0.y += b1;
                    v1.x += b0; v1.y += b1;
                }
                if (r0 < M) *(float2*)&C[(size_t)r0 * ldc + col] = v0;
                if (r1 < M) *(float2*)&C[(size_t)r1 * ldc + col] = v1;
            }
        }
    }
}

// ---------------- CSR aggregation (fp16 sources, fp32 accum) ----------------
// out[d] = sum_e w * hwh[src] + hwh[d]/deg + bias ; warp per node.
__global__ __launch_bounds__(256) void k_aggr(
    const int* __restrict__ rowptr, const int* __restrict__ csrc,
    const float* __restrict__ cw, const __half2* __restrict__ hwh,
    const float* __restrict__ deg, const float* __restrict__ bias,
    float4* __restrict__ out, int ldo4)
{
    int node = (blockIdx.x * blockDim.x + threadIdx.x) >> 5;
    if (node >= NN) return;
    int lane = threadIdx.x & 31;

    const uint2* mh = (const uint2*)hwh;   // 32 uint2 per node row

    auto loadf4 = [&](int n) -> float4 {
        uint2 p = __ldg(&mh[(size_t)n * 32 + lane]);
        __half2 h0 = *(__half2*)&p.x;
        __half2 h1 = *(__half2*)&p.y;
        float2 f0 = __half22float2(h0);
        float2 f1 = __half22float2(h1);
        return make_float4(f0.x, f0.y, f1.x, f1.y);
    };

    float sn = 1.0f / deg[node];
    float4 self = loadf4(node);
    float4 bb = ((const float4*)bias)[lane];
    float4 acc;
    acc.x = self.x * sn + bb.x;
    acc.y = self.y * sn + bb.y;
    acc.z = self.z * sn + bb.z;
    acc.w = self.w * sn + bb.w;

    int e  = rowptr[node];
    int e1 = rowptr[node + 1];
    for (; e + 3 < e1; e += 4) {
        int   s0 = __ldg(&csrc[e]),     s1 = __ldg(&csrc[e + 1]);
        int   s2 = __ldg(&csrc[e + 2]), s3 = __ldg(&csrc[e + 3]);
        float w0 = __ldg(&cw[e]),       w1 = __ldg(&cw[e + 1]);
        float w2 = __ldg(&cw[e + 2]),   w3 = __ldg(&cw[e + 3]);
        float4 v0 = loadf4(s0), v1 = loadf4(s1), v2 = loadf4(s2), v3 = loadf4(s3);
        acc.x += w0 * v0.x + w1 * v1.x + w2 * v2.x + w3 * v3.x;
        acc.y += w0 * v0.y + w1 * v1.y + w2 * v2.y + w3 * v3.y;
        acc.z += w0 * v0.z + w1 * v1.z + w2 * v2.z + w3 * v3.z;
        acc.w += w0 * v0.w + w1 * v1.w + w2 * v2.w + w3 * v3.w;
    }
    for (; e < e1; e++) {
        int   s0 = __ldg(&csrc[e]);
        float w0 = __ldg(&cw[e]);
        float4 v0 = loadf4(s0);
        acc.x += w0 * v0.x;
        acc.y += w0 * v0.y;
        acc.z += w0 * v0.z;
        acc.w += w0 * v0.w;
    }
    out[(size_t)node * ldo4 + lane] = acc;
}

// ---------------- final: out = cat @ W_out + b_out (3xTF32) -----------------
// 256-row tile, 8 warps (32 rows each), N=40, K=640, BK=16.
#define LDO 264   // 264 mod 32 == 8

__global__ __launch_bounds__(256) void k_out(
    const float* __restrict__ cat,
    const uint32_t* __restrict__ Woh, const uint32_t* __restrict__ Wol,
    const float* __restrict__ b, float* __restrict__ out)
{
    __shared__ uint32_t Ah[BK * LDO], Al[BK * LDO];
    __shared__ uint32_t Bh[BK * 40], Bl[BK * 40];

    const int tid  = threadIdx.x;
    const int wid  = tid >> 5;
    const int lane = tid & 31;
    const int g    = lane >> 2;
    const int tg   = lane & 3;
    const int wm   = wid * 32;
    const int brow = blockIdx.x * 256;

    float acc[2][5][4];
#pragma unroll
    for (int mt = 0; mt < 2; mt++)
#pragma unroll
        for (int nt = 0; nt < 5; nt++)
#pragma unroll
            for (int j = 0; j < 4; j++) acc[mt][nt][j] = 0.0f;

    for (int kc = 0; kc < NCAT; kc += BK) {
        // A tile 256x16 = 1024 float4, 4 per thread
#pragma unroll
        for (int l = 0; l < 4; l++) {
            int v  = tid + l * 256;
            int r  = v >> 2;
            int c4 = (v & 3) * 4;
            int grow = brow + r;
            float4 av = make_float4(0.f, 0.f, 0.f, 0.f);
            if (grow < NN) av = *(const float4*)&cat[(size_t)grow * NCAT + kc + c4];
            float aa[4] = {av.x, av.y, av.z, av.w};
#pragma unroll
            for (int j = 0; j < 4; j++) {
                uint32_t hb = f2tf32(aa[j]);
                Ah[(c4 + j) * LDO + r] = hb;
                Al[(c4 + j) * LDO + r] = f2tf32(aa[j] - __uint_as_float(hb));
            }
        }
        // B tile 16x40 = 640, pre-split, contiguous copy
        for (int idx = tid; idx < BK * 40; idx += 256) {
            Bh[idx] = Woh[kc * 40 + idx];
            Bl[idx] = Wol[kc * 40 + idx];
        }
        __syncthreads();

#pragma unroll
        for (int ks = 0; ks < 2; ks++) {
            int k0 = ks * 8;
            uint32_t ahf[2][4], alf[2][4];
#pragma unroll
            for (int mt = 0; mt < 2; mt++) {
                int m0 = wm + mt * 16;
                ahf[mt][0] = Ah[(k0 + tg) * LDO + m0 + g];
                ahf[mt][1] = Ah[(k0 + tg) * LDO + m0 + g + 8];
                ahf[mt][2] = Ah[(k0 + tg + 4) * LDO + m0 + g];
                ahf[mt][3] = Ah[(k0 + tg + 4) * LDO + m0 + g + 8];
                alf[mt][0] = Al[(k0 + tg) * LDO + m0 + g];
                alf[mt][1] = Al[(k0 + tg) * LDO + m0 + g + 8];
                alf[mt][2] = Al[(k0 + tg + 4) * LDO + m0 + g];
                alf[mt][3] = Al[(k0 + tg + 4) * LDO + m0 + g + 8];
            }
#pragma unroll
            for (int nt = 0; nt < 5; nt++) {
                int n0 = nt * 8;
                uint32_t b0h = Bh[(k0 + tg) * 40 + n0 + g];
                uint32_t b1h = Bh[(k0 + tg + 4) * 40 + n0 + g];
                uint32_t b0l = Bl[(k0 + tg) * 40 + n0 + g];
                uint32_t b1l = Bl[(k0 + tg + 4) * 40 + n0 + g];
#pragma unroll
                for (int mt = 0; mt < 2; mt++) {
                    mma_tf32(acc[mt][nt], ahf[mt], b0h, b1h);
                    mma_tf32(acc[mt][nt], alf[mt], b0h, b1h);
                    mma_tf32(acc[mt][nt], ahf[mt], b0l, b1l);
                }
            }
        }
        __syncthreads();
    }

#pragma unroll
    for (int mt = 0; mt < 2; mt++) {
        int r0 = brow + wm + mt * 16 + g;
        int r1 = r0 + 8;
#pragma unroll
        for (int nt = 0; nt < 5; nt++) {
            int col = nt * 8 + tg * 2;
            float b0 = b[col], b1 = b[col + 1];
            if (r0 < NN) {
                float2 v = make_float2(acc[mt][nt][0] + b0, acc[mt][nt][1] + b1);
                *(float2*)&out[(size_t)r0 * CC + col] = v;
            }
            if (r1 < NN) {
                float2 v = make_float2(acc[mt][nt][2] + b0, acc[mt][nt][3] + b1);
                *(float2*)&out[(size_t)r1 * CC + col] = v;
            }
        }
    }
}

// ---------------- launch -----------------------------------------------------
extern "C" void kernel_launch(void* const* d_in, const int* in_sizes, int n_in,
                              void* d_out, int out_size) {
    const float* x     = (const float*)d_in[0];
    const int*   ei    = (const int*)  d_in[1];
    const float* ew    = (const float*)d_in[2];
    const float* W_in  = (const float*)d_in[3];
    const float* b_in  = (const float*)d_in[4];
    const float* W_gcn = (const float*)d_in[5];
    const float* b_gcn = (const float*)d_in[6];
    const float* W_out = (const float*)d_in[7];
    const float* b_out = (const float*)d_in[8];
    float* out = (float*)d_out;

    float *deg, *t0, *t1, *cat, *cw;
    __half2* hwh;
    uint32_t *bh, *bl, *woh, *wol;
    int *cnt, *rowptr, *cursor, *csrc, *bsum, *boff;
    cudaGetSymbolAddress((void**)&deg,    g_deg);
    cudaGetSymbolAddress((void**)&hwh,    g_hwh);
    cudaGetSymbolAddress((void**)&t0,     g_t0);
    cudaGetSymbolAddress((void**)&t1,     g_t1);
    cudaGetSymbolAddress((void**)&cat,    g_cat);
    cudaGetSymbolAddress((void**)&bh,     g_bh);
    cudaGetSymbolAddress((void**)&bl,     g_bl);
    cudaGetSymbolAddress((void**)&woh,    g_woh);
    cudaGetSymbolAddress((void**)&wol,    g_wol);
    cudaGetSymbolAddress((void**)&cnt,    g_cnt);
    cudaGetSymbolAddress((void**)&rowptr, g_rowptr);
    cudaGetSymbolAddress((void**)&cursor, g_cursor);
    cudaGetSymbolAddress((void**)&csrc,   g_csrc);
    cudaGetSymbolAddress((void**)&cw,     g_cw);
    cudaGetSymbolAddress((void**)&bsum,   g_bsum);
    cudaGetSymbolAddress((void**)&boff,   g_boff);

    // weight pre-split + degree + CSR
    k_wsplit  <<<(WMAIN + WOUTN + 255) / 256, 256>>>(W_in, W_gcn, W_out,
                                                     bh, bl, woh, wol);
    k_deg_init<<<(NN + 255) / 256, 256>>>(deg, cnt);
    k_deg_acc <<<(EE + 255) / 256, 256>>>(ei, ew, deg, cnt);
    k_scan1   <<<NB_SCAN, 256>>>(cnt, bsum);
    k_scan2   <<<1, 256>>>(bsum, boff, rowptr);
    k_scan3   <<<NB_SCAN, 256>>>(cnt, boff, rowptr, cursor);
    k_fill    <<<(EE + 255) / 256, 256>>>(ei, ew, deg, cursor, csrc, cw);

    const int gb = (NN + 127) / 128;

    // h = x @ W_in + b_in -> cat[:, 0:128] (fp32)
    k_mma<<<gb, 256>>>(x, FF, bh, bl, b_in, cat, NCAT, nullptr, NN, FF);

    // one GCN conv: hwh = fp16(in @ Wk); dst = aggr + self + bias
    auto gcn = [&](const float* in, int lda, int k, float* dst, int ldo) {
        k_mma <<<gb, 256>>>(in, lda, bh + FF * HH + (size_t)k * HH * HH,
                            bl + FF * HH + (size_t)k * HH * HH,
                            nullptr, nullptr, 0, hwh, NN, HH);
        k_aggr<<<(NN * 32 + 255) / 256, 256>>>(rowptr, csrc, cw, hwh, deg,
                                               b_gcn + (size_t)k * HH,
                                               (float4*)dst, ldo / 4);
    };

    const float* h = cat;                       // stride NCAT

    gcn(h,  NCAT, 0, cat + 1 * HH, NCAT);       // chain 1

    gcn(h,  NCAT, 1, t0, HH);                   // chain 2
    gcn(t0, HH,   2, cat + 2 * HH, NCAT);

    gcn(h,  NCAT, 3, t0, HH);                   // chain 3
    gcn(t0, HH,   4, t1, HH);
    gcn(t1, HH,   5, cat + 3 * HH, NCAT);

    gcn(h,  NCAT, 6, t0, HH);                   // chain 4
    gcn(t0, HH,   7, t1, HH);
    gcn(t1, HH,   8, t0, HH);
    gcn(t0, HH,   9, cat + 4 * HH, NCAT);

    // out = cat @ W_out + b_out (tensor cores)
    k_out<<<(NN + 255) / 256, 256>>>(cat, woh, wol, b_out, out);
}